// round 3
// baseline (speedup 1.0000x reference)
#include <cuda_runtime.h>
#include <math.h>

// Shapes (fixed for this problem)
#define BATCH 16
#define SEQL  128
#define DIM   768
#define NH1   770
#define NOUT  40
#define NPAIR 3405
#define LP1   129     // L+1 rows per batch in hidden_states
#define PST   772     // padded row stride for P/Q (float4-aligned)

// Scratch: P = X @ W1i, Q = X @ W1j   (X = hidden[:,1:129,:] flattened to 2048 rows)
// +64 pad so guarded-garbage float4 reads past row 770 stay in bounds.
__device__ float g_P[(size_t)BATCH * SEQL * PST + 64];
__device__ float g_Q[(size_t)BATCH * SEQL * PST + 64];
__device__ int   g_vi[NPAIR];
__device__ int   g_vj[NPAIR];

// ---------------------------------------------------------------------------
// Pair table: row-major nonzero order of ((j>=i) & (j-i<30)) for L=128.
// Rows 0..98 have 30 pairs; row i>=99 has 128-i pairs.
// ---------------------------------------------------------------------------
__global__ void fill_pairs_kernel() {
    int i = threadIdx.x;
    if (i >= SEQL) return;
    int cnt = min(30, SEQL - i);
    int base = (i < 99) ? 30 * i
                        : 2970 + 435 - ((SEQL - i) * (SEQL + 1 - i)) / 2;
    for (int t = 0; t < cnt; t++) {
        g_vi[base + t] = i;
        g_vj[base + t] = i + t;
    }
}

// ---------------------------------------------------------------------------
// Kernel 1: 2048 x 768 x 770 fp32 GEMM, z=0 -> P (W1 rows 0..767),
//                                      z=1 -> Q (W1 rows 768..1535).
// 128x128 tile per 256-thread block, 8x8 register micro-tile, BK=16.
// ---------------------------------------------------------------------------
#define BM  128
#define BN  128
#define BKK 16

__global__ __launch_bounds__(256, 2)
void gemm1_kernel(const float* __restrict__ hidden, const float* __restrict__ W1) {
    const int n0 = blockIdx.x * BN;
    const int m0 = blockIdx.y * BM;
    const float* W = W1 + (size_t)blockIdx.z * DIM * NH1;
    float* Cout = (blockIdx.z == 0) ? g_P : g_Q;

    __shared__ float As[BKK][BM];
    __shared__ float Bs[BKK][BN];

    const int tid = threadIdx.x;
    const int tx = tid & 15;   // col group (8 cols)
    const int ty = tid >> 4;   // row group (8 rows)

    float acc[8][8];
    #pragma unroll
    for (int i = 0; i < 8; i++)
        #pragma unroll
        for (int j = 0; j < 8; j++) acc[i][j] = 0.f;

    // A-load mapping: 128 rows x 16 k = 2 float4 per thread
    const int a_k4 = tid & 3;   // which float4 of the 16-wide k slab
    const int a_r  = tid >> 2;  // rows a_r and a_r+64
    // B-load mapping: 16 k x 128 n = 4 float2 per thread
    const int b_n2 = tid & 63;  // col = b_n2*2
    const int b_k  = tid >> 6;  // k rows b_k, +4, +8, +12

    const float* aptr[2];
    #pragma unroll
    for (int rr = 0; rr < 2; rr++) {
        int m = m0 + a_r + rr * 64;
        int bb = m >> 7, t = m & 127;
        aptr[rr] = hidden + (size_t)(bb * LP1 + t + 1) * DIM + a_k4 * 4;
    }

    const int ncol = n0 + b_n2 * 2;
    for (int k0 = 0; k0 < DIM; k0 += BKK) {
        #pragma unroll
        for (int rr = 0; rr < 2; rr++) {
            float4 v = *(const float4*)(aptr[rr] + k0);
            As[a_k4*4+0][a_r + rr*64] = v.x;
            As[a_k4*4+1][a_r + rr*64] = v.y;
            As[a_k4*4+2][a_r + rr*64] = v.z;
            As[a_k4*4+3][a_r + rr*64] = v.w;
        }
        #pragma unroll
        for (int kk = 0; kk < 4; kk++) {
            int k = b_k + kk * 4;
            float2 v = make_float2(0.f, 0.f);
            if (ncol + 1 < NH1)  // ncol always even; last valid pair is 768/769
                v = *(const float2*)(W + (size_t)(k0 + k) * NH1 + ncol);
            Bs[k][b_n2*2+0] = v.x;
            Bs[k][b_n2*2+1] = v.y;
        }
        __syncthreads();
        #pragma unroll
        for (int kk = 0; kk < BKK; kk++) {
            float a[8], bf[8];
            #pragma unroll
            for (int i = 0; i < 8; i++) a[i]  = As[kk][ty*8 + i];
            #pragma unroll
            for (int j = 0; j < 8; j++) bf[j] = Bs[kk][tx*8 + j];
            #pragma unroll
            for (int i = 0; i < 8; i++)
                #pragma unroll
                for (int j = 0; j < 8; j++)
                    acc[i][j] = fmaf(a[i], bf[j], acc[i][j]);
        }
        __syncthreads();
    }

    #pragma unroll
    for (int i = 0; i < 8; i++) {
        size_t mrow = (size_t)(m0 + ty*8 + i) * PST;
        #pragma unroll
        for (int j = 0; j < 8; j++) {
            int nn = n0 + tx*8 + j;
            if (nn < NH1) Cout[mrow + nn] = acc[i][j];
        }
    }
}

// ---------------------------------------------------------------------------
// Kernel 2: per (batch, 128-pair chunk):
//   Ht[k][r] = relu(P[vi_r][k] + Q[vj_r][k] + ind_r*w1c[k] + b1[k])
//   logits   = Ht^T @ W2 + b2, then row-wise log_softmax.
// 128 pairs x 40 outs per block, K tiles of 32, 4x5 register micro-tile.
// ---------------------------------------------------------------------------
#define BP  128
#define BK2 32
#define HTS (BP + 4)   // 132, keeps float4 alignment on Ht rows

__global__ __launch_bounds__(256, 2)
void span_head_kernel(const float* __restrict__ W1, const float* __restrict__ bias1,
                      const float* __restrict__ W2, const float* __restrict__ bias2,
                      const int* __restrict__ spans, float* __restrict__ out) {
    const int b  = blockIdx.y;
    const int p0 = blockIdx.x * BP;
    const int tid = threadIdx.x;

    __shared__ float Ht[BK2][HTS];
    __shared__ float W2s[BK2 * NOUT];
    __shared__ int   s_ri[BP];
    __shared__ int   s_rj[BP];
    __shared__ float s_ind[BP];
    __shared__ float Lg[BP][NOUT + 1];

    const float* w1c = W1 + (size_t)2 * DIM * NH1;  // row 1536 of W1

    if (tid < BP) {
        int p = p0 + tid;
        int i = 0, j = 0;
        float ind = 0.f;
        if (p < NPAIR) {
            i = g_vi[p];
            j = g_vj[p];
            int s = spans[b*2 + 0];
            int e = spans[b*2 + 1];
            if (i == s && j == e)      ind = 2.f;
            else if (i >= s && j <= e) ind = 1.f;
        }
        s_ri[tid]  = (b * SEQL + i) * PST;
        s_rj[tid]  = (b * SEQL + j) * PST;
        s_ind[tid] = ind;
    }
    __syncthreads();

    const int tx   = tid & 7;   // 8 col groups of 5 outputs
    const int ty   = tid >> 3;  // 32 row groups of 4 pairs
    const int g_kq = tid & 7;   // float4 index within the 32-wide k slab
    const int g_r0 = tid >> 3;  // base row for gather (rows g_r0 + 32w)

    float acc[4][5];
    #pragma unroll
    for (int i = 0; i < 4; i++)
        #pragma unroll
        for (int j = 0; j < 5; j++) acc[i][j] = 0.f;

    for (int k0 = 0; k0 < NH1; k0 += BK2) {
        // --- W2 tile: 32x40 = 1280 floats, coalesced linear copy ---
        #pragma unroll
        for (int u = 0; u < 5; u++) {
            int idx = u * 256 + tid;
            int g   = k0 * NOUT + idx;
            W2s[idx] = (g < NH1 * NOUT) ? W2[g] : 0.f;
        }
        // --- gather + bias + relu into Ht (transposed) ---
        const int kb = k0 + g_kq * 4;
        float4 c1, c2;
        if (kb + 3 < NH1) {
            c1 = *(const float4*)(w1c + kb);
            c2 = *(const float4*)(bias1 + kb);
        } else {
            c1.x = (kb+0 < NH1) ? w1c[kb+0] : 0.f;
            c1.y = (kb+1 < NH1) ? w1c[kb+1] : 0.f;
            c1.z = (kb+2 < NH1) ? w1c[kb+2] : 0.f;
            c1.w = (kb+3 < NH1) ? w1c[kb+3] : 0.f;
            c2.x = (kb+0 < NH1) ? bias1[kb+0] : 0.f;
            c2.y = (kb+1 < NH1) ? bias1[kb+1] : 0.f;
            c2.z = (kb+2 < NH1) ? bias1[kb+2] : 0.f;
            c2.w = (kb+3 < NH1) ? bias1[kb+3] : 0.f;
        }
        const int kl = g_kq * 4;
        #pragma unroll
        for (int w = 0; w < 4; w++) {
            int r = g_r0 + w * 32;
            float4 p4 = *(const float4*)(g_P + s_ri[r] + kb);
            float4 q4 = *(const float4*)(g_Q + s_rj[r] + kb);
            float ind = s_ind[r];
            // k >= 770 lanes produce finite garbage, but W2s is 0 there -> no effect
            Ht[kl+0][r] = fmaxf(fmaf(ind, c1.x, p4.x + q4.x + c2.x), 0.f);
            Ht[kl+1][r] = fmaxf(fmaf(ind, c1.y, p4.y + q4.y + c2.y), 0.f);
            Ht[kl+2][r] = fmaxf(fmaf(ind, c1.z, p4.z + q4.z + c2.z), 0.f);
            Ht[kl+3][r] = fmaxf(fmaf(ind, c1.w, p4.w + q4.w + c2.w), 0.f);
        }
        __syncthreads();
        // --- 4x5 micro-tile FMA over 32 k ---
        #pragma unroll
        for (int kk = 0; kk < BK2; kk++) {
            float4 a4 = *(const float4*)&Ht[kk][ty * 4];
            const float* wrow = &W2s[kk * NOUT + tx * 5];
            float b0 = wrow[0], b1v = wrow[1], b2v = wrow[2], b3v = wrow[3], b4v = wrow[4];
            acc[0][0] = fmaf(a4.x, b0, acc[0][0]);
            acc[0][1] = fmaf(a4.x, b1v, acc[0][1]);
            acc[0][2] = fmaf(a4.x, b2v, acc[0][2]);
            acc[0][3] = fmaf(a4.x, b3v, acc[0][3]);
            acc[0][4] = fmaf(a4.x, b4v, acc[0][4]);
            acc[1][0] = fmaf(a4.y, b0, acc[1][0]);
            acc[1][1] = fmaf(a4.y, b1v, acc[1][1]);
            acc[1][2] = fmaf(a4.y, b2v, acc[1][2]);
            acc[1][3] = fmaf(a4.y, b3v, acc[1][3]);
            acc[1][4] = fmaf(a4.y, b4v, acc[1][4]);
            acc[2][0] = fmaf(a4.z, b0, acc[2][0]);
            acc[2][1] = fmaf(a4.z, b1v, acc[2][1]);
            acc[2][2] = fmaf(a4.z, b2v, acc[2][2]);
            acc[2][3] = fmaf(a4.z, b3v, acc[2][3]);
            acc[2][4] = fmaf(a4.z, b4v, acc[2][4]);
            acc[3][0] = fmaf(a4.w, b0, acc[3][0]);
            acc[3][1] = fmaf(a4.w, b1v, acc[3][1]);
            acc[3][2] = fmaf(a4.w, b2v, acc[3][2]);
            acc[3][3] = fmaf(a4.w, b3v, acc[3][3]);
            acc[3][4] = fmaf(a4.w, b4v, acc[3][4]);
        }
        __syncthreads();
    }

    // logits + b2 into shared
    #pragma unroll
    for (int i = 0; i < 4; i++)
        #pragma unroll
        for (int j = 0; j < 5; j++)
            Lg[ty*4 + i][tx*5 + j] = acc[i][j] + bias2[tx*5 + j];
    __syncthreads();

    // log_softmax per pair row + store
    if (tid < BP) {
        int p = p0 + tid;
        if (p < NPAIR) {
            float mx = Lg[tid][0];
            #pragma unroll
            for (int o = 1; o < NOUT; o++) mx = fmaxf(mx, Lg[tid][o]);
            float sum = 0.f;
            #pragma unroll
            for (int o = 0; o < NOUT; o++) sum += expf(Lg[tid][o] - mx);
            float lse = mx + logf(sum);
            float* op = out + ((size_t)b * NPAIR + p) * NOUT;
            #pragma unroll
            for (int o = 0; o < NOUT; o++) op[o] = Lg[tid][o] - lse;
        }
    }
}

// ---------------------------------------------------------------------------
// Launch. Inputs (metadata order): hidden_states, pred_spans, token_num,
// span_available_indication_matrix, W1, b1, W2, b2. Output fp32 [16,3405,40].
// ---------------------------------------------------------------------------
extern "C" void kernel_launch(void* const* d_in, const int* in_sizes, int n_in,
                              void* d_out, int out_size) {
    const float* hidden = (const float*)d_in[0];
    const int*   spans  = (const int*)d_in[1];
    // d_in[2] token_num (==128) and d_in[3] span mask are implied by the
    // fixed band structure; pair table is rebuilt analytically each call.
    const float* W1 = (const float*)d_in[4];
    const float* b1 = (const float*)d_in[5];
    const float* W2 = (const float*)d_in[6];
    const float* b2 = (const float*)d_in[7];
    float* out = (float*)d_out;

    fill_pairs_kernel<<<1, 128>>>();
    gemm1_kernel<<<dim3((NH1 + BN - 1) / BN, (BATCH * SEQL) / BM, 2), 256>>>(hidden, W1);
    span_head_kernel<<<dim3((NPAIR + BP - 1) / BP, BATCH), 256>>>(W1, b1, W2, b2, spans, out);
}

// round 4
// speedup vs baseline: 1.0002x; 1.0002x over previous
#include <cuda_runtime.h>
#include <math.h>

// Shapes (fixed for this problem)
#define BATCH 16
#define SEQL  128
#define DIM   768
#define NH1   770
#define NOUT  40
#define NPAIR 3405
#define LP1   129     // L+1 rows per batch in hidden_states
#define PST   772     // padded row stride for P/Q (float4-aligned)

// Scratch: P = X @ W1i, Q = X @ W1j   (X = hidden[:,1:129,:] flattened to 2048 rows)
// +64 pad so guarded-garbage float4 reads past row 770 stay in bounds.
__device__ float g_P[(size_t)BATCH * SEQL * PST + 64];
__device__ float g_Q[(size_t)BATCH * SEQL * PST + 64];
__device__ int   g_vi[NPAIR];
__device__ int   g_vj[NPAIR];

// ---------------------------------------------------------------------------
// Pair table: row-major nonzero order of ((j>=i) & (j-i<30)) for L=128.
// Rows 0..98 have 30 pairs; row i>=99 has 128-i pairs.
// ---------------------------------------------------------------------------
__global__ void fill_pairs_kernel() {
    int i = threadIdx.x;
    if (i >= SEQL) return;
    int cnt = min(30, SEQL - i);
    int base = (i < 99) ? 30 * i
                        : 2970 + 435 - ((SEQL - i) * (SEQL + 1 - i)) / 2;
    for (int t = 0; t < cnt; t++) {
        g_vi[base + t] = i;
        g_vj[base + t] = i + t;
    }
}

// ---------------------------------------------------------------------------
// Kernel 1: 2048 x 768 x 770 fp32 GEMM, z=0 -> P (W1 rows 0..767),
//                                      z=1 -> Q (W1 rows 768..1535).
// 128x128 tile per 256-thread block, 8x8 register micro-tile, BK=16.
// ---------------------------------------------------------------------------
#define BM  128
#define BN  128
#define BKK 16

__global__ __launch_bounds__(256, 2)
void gemm1_kernel(const float* __restrict__ hidden, const float* __restrict__ W1) {
    const int n0 = blockIdx.x * BN;
    const int m0 = blockIdx.y * BM;
    const float* W = W1 + (size_t)blockIdx.z * DIM * NH1;
    float* Cout = (blockIdx.z == 0) ? g_P : g_Q;

    __shared__ float As[BKK][BM];
    __shared__ float Bs[BKK][BN];

    const int tid = threadIdx.x;
    const int tx = tid & 15;   // col group (8 cols)
    const int ty = tid >> 4;   // row group (8 rows)

    float acc[8][8];
    #pragma unroll
    for (int i = 0; i < 8; i++)
        #pragma unroll
        for (int j = 0; j < 8; j++) acc[i][j] = 0.f;

    // A-load mapping: 128 rows x 16 k = 2 float4 per thread
    const int a_k4 = tid & 3;   // which float4 of the 16-wide k slab
    const int a_r  = tid >> 2;  // rows a_r and a_r+64
    // B-load mapping: 16 k x 128 n = 4 float2 per thread
    const int b_n2 = tid & 63;  // col = b_n2*2
    const int b_k  = tid >> 6;  // k rows b_k, +4, +8, +12

    const float* aptr[2];
    #pragma unroll
    for (int rr = 0; rr < 2; rr++) {
        int m = m0 + a_r + rr * 64;
        int bb = m >> 7, t = m & 127;
        aptr[rr] = hidden + (size_t)(bb * LP1 + t + 1) * DIM + a_k4 * 4;
    }

    const int ncol = n0 + b_n2 * 2;
    for (int k0 = 0; k0 < DIM; k0 += BKK) {
        #pragma unroll
        for (int rr = 0; rr < 2; rr++) {
            float4 v = *(const float4*)(aptr[rr] + k0);
            As[a_k4*4+0][a_r + rr*64] = v.x;
            As[a_k4*4+1][a_r + rr*64] = v.y;
            As[a_k4*4+2][a_r + rr*64] = v.z;
            As[a_k4*4+3][a_r + rr*64] = v.w;
        }
        #pragma unroll
        for (int kk = 0; kk < 4; kk++) {
            int k = b_k + kk * 4;
            float2 v = make_float2(0.f, 0.f);
            if (ncol + 1 < NH1)  // ncol always even; last valid pair is 768/769
                v = *(const float2*)(W + (size_t)(k0 + k) * NH1 + ncol);
            Bs[k][b_n2*2+0] = v.x;
            Bs[k][b_n2*2+1] = v.y;
        }
        __syncthreads();
        #pragma unroll
        for (int kk = 0; kk < BKK; kk++) {
            float a[8], bf[8];
            #pragma unroll
            for (int i = 0; i < 8; i++) a[i]  = As[kk][ty*8 + i];
            #pragma unroll
            for (int j = 0; j < 8; j++) bf[j] = Bs[kk][tx*8 + j];
            #pragma unroll
            for (int i = 0; i < 8; i++)
                #pragma unroll
                for (int j = 0; j < 8; j++)
                    acc[i][j] = fmaf(a[i], bf[j], acc[i][j]);
        }
        __syncthreads();
    }

    #pragma unroll
    for (int i = 0; i < 8; i++) {
        size_t mrow = (size_t)(m0 + ty*8 + i) * PST;
        #pragma unroll
        for (int j = 0; j < 8; j++) {
            int nn = n0 + tx*8 + j;
            if (nn < NH1) Cout[mrow + nn] = acc[i][j];
        }
    }
}

// ---------------------------------------------------------------------------
// Kernel 2: per (batch, 128-pair chunk):
//   Ht[k][r] = relu(P[vi_r][k] + Q[vj_r][k] + ind_r*w1c[k] + b1[k])
//   logits   = Ht^T @ W2 + b2, then row-wise log_softmax.
// 128 pairs x 40 outs per block, K tiles of 32, 4x5 register micro-tile.
// ---------------------------------------------------------------------------
#define BP  128
#define BK2 32
#define HTS (BP + 4)   // 132, keeps float4 alignment on Ht rows

__global__ __launch_bounds__(256, 2)
void span_head_kernel(const float* __restrict__ W1, const float* __restrict__ bias1,
                      const float* __restrict__ W2, const float* __restrict__ bias2,
                      const int* __restrict__ spans, float* __restrict__ out) {
    const int b  = blockIdx.y;
    const int p0 = blockIdx.x * BP;
    const int tid = threadIdx.x;

    __shared__ float Ht[BK2][HTS];
    __shared__ float W2s[BK2 * NOUT];
    __shared__ int   s_ri[BP];
    __shared__ int   s_rj[BP];
    __shared__ float s_ind[BP];
    __shared__ float Lg[BP][NOUT + 1];

    const float* w1c = W1 + (size_t)2 * DIM * NH1;  // row 1536 of W1

    if (tid < BP) {
        int p = p0 + tid;
        int i = 0, j = 0;
        float ind = 0.f;
        if (p < NPAIR) {
            i = g_vi[p];
            j = g_vj[p];
            int s = spans[b*2 + 0];
            int e = spans[b*2 + 1];
            if (i == s && j == e)      ind = 2.f;
            else if (i >= s && j <= e) ind = 1.f;
        }
        s_ri[tid]  = (b * SEQL + i) * PST;
        s_rj[tid]  = (b * SEQL + j) * PST;
        s_ind[tid] = ind;
    }
    __syncthreads();

    const int tx   = tid & 7;   // 8 col groups of 5 outputs
    const int ty   = tid >> 3;  // 32 row groups of 4 pairs
    const int g_kq = tid & 7;   // float4 index within the 32-wide k slab
    const int g_r0 = tid >> 3;  // base row for gather (rows g_r0 + 32w)

    float acc[4][5];
    #pragma unroll
    for (int i = 0; i < 4; i++)
        #pragma unroll
        for (int j = 0; j < 5; j++) acc[i][j] = 0.f;

    for (int k0 = 0; k0 < NH1; k0 += BK2) {
        // --- W2 tile: 32x40 = 1280 floats, coalesced linear copy ---
        #pragma unroll
        for (int u = 0; u < 5; u++) {
            int idx = u * 256 + tid;
            int g   = k0 * NOUT + idx;
            W2s[idx] = (g < NH1 * NOUT) ? W2[g] : 0.f;
        }
        // --- gather + bias + relu into Ht (transposed) ---
        const int kb = k0 + g_kq * 4;
        float4 c1, c2;
        if (kb + 3 < NH1) {
            c1 = *(const float4*)(w1c + kb);
            c2 = *(const float4*)(bias1 + kb);
        } else {
            c1.x = (kb+0 < NH1) ? w1c[kb+0] : 0.f;
            c1.y = (kb+1 < NH1) ? w1c[kb+1] : 0.f;
            c1.z = (kb+2 < NH1) ? w1c[kb+2] : 0.f;
            c1.w = (kb+3 < NH1) ? w1c[kb+3] : 0.f;
            c2.x = (kb+0 < NH1) ? bias1[kb+0] : 0.f;
            c2.y = (kb+1 < NH1) ? bias1[kb+1] : 0.f;
            c2.z = (kb+2 < NH1) ? bias1[kb+2] : 0.f;
            c2.w = (kb+3 < NH1) ? bias1[kb+3] : 0.f;
        }
        const int kl = g_kq * 4;
        #pragma unroll
        for (int w = 0; w < 4; w++) {
            int r = g_r0 + w * 32;
            float4 p4 = *(const float4*)(g_P + s_ri[r] + kb);
            float4 q4 = *(const float4*)(g_Q + s_rj[r] + kb);
            float ind = s_ind[r];
            // k >= 770 lanes produce finite garbage, but W2s is 0 there -> no effect
            Ht[kl+0][r] = fmaxf(fmaf(ind, c1.x, p4.x + q4.x + c2.x), 0.f);
            Ht[kl+1][r] = fmaxf(fmaf(ind, c1.y, p4.y + q4.y + c2.y), 0.f);
            Ht[kl+2][r] = fmaxf(fmaf(ind, c1.z, p4.z + q4.z + c2.z), 0.f);
            Ht[kl+3][r] = fmaxf(fmaf(ind, c1.w, p4.w + q4.w + c2.w), 0.f);
        }
        __syncthreads();
        // --- 4x5 micro-tile FMA over 32 k ---
        #pragma unroll
        for (int kk = 0; kk < BK2; kk++) {
            float4 a4 = *(const float4*)&Ht[kk][ty * 4];
            const float* wrow = &W2s[kk * NOUT + tx * 5];
            float b0 = wrow[0], b1v = wrow[1], b2v = wrow[2], b3v = wrow[3], b4v = wrow[4];
            acc[0][0] = fmaf(a4.x, b0, acc[0][0]);
            acc[0][1] = fmaf(a4.x, b1v, acc[0][1]);
            acc[0][2] = fmaf(a4.x, b2v, acc[0][2]);
            acc[0][3] = fmaf(a4.x, b3v, acc[0][3]);
            acc[0][4] = fmaf(a4.x, b4v, acc[0][4]);
            acc[1][0] = fmaf(a4.y, b0, acc[1][0]);
            acc[1][1] = fmaf(a4.y, b1v, acc[1][1]);
            acc[1][2] = fmaf(a4.y, b2v, acc[1][2]);
            acc[1][3] = fmaf(a4.y, b3v, acc[1][3]);
            acc[1][4] = fmaf(a4.y, b4v, acc[1][4]);
            acc[2][0] = fmaf(a4.z, b0, acc[2][0]);
            acc[2][1] = fmaf(a4.z, b1v, acc[2][1]);
            acc[2][2] = fmaf(a4.z, b2v, acc[2][2]);
            acc[2][3] = fmaf(a4.z, b3v, acc[2][3]);
            acc[2][4] = fmaf(a4.z, b4v, acc[2][4]);
            acc[3][0] = fmaf(a4.w, b0, acc[3][0]);
            acc[3][1] = fmaf(a4.w, b1v, acc[3][1]);
            acc[3][2] = fmaf(a4.w, b2v, acc[3][2]);
            acc[3][3] = fmaf(a4.w, b3v, acc[3][3]);
            acc[3][4] = fmaf(a4.w, b4v, acc[3][4]);
        }
        __syncthreads();
    }

    // logits + b2 into shared
    #pragma unroll
    for (int i = 0; i < 4; i++)
        #pragma unroll
        for (int j = 0; j < 5; j++)
            Lg[ty*4 + i][tx*5 + j] = acc[i][j] + bias2[tx*5 + j];
    __syncthreads();

    // log_softmax per pair row + store
    if (tid < BP) {
        int p = p0 + tid;
        if (p < NPAIR) {
            float mx = Lg[tid][0];
            #pragma unroll
            for (int o = 1; o < NOUT; o++) mx = fmaxf(mx, Lg[tid][o]);
            float sum = 0.f;
            #pragma unroll
            for (int o = 0; o < NOUT; o++) sum += expf(Lg[tid][o] - mx);
            float lse = mx + logf(sum);
            float* op = out + ((size_t)b * NPAIR + p) * NOUT;
            #pragma unroll
            for (int o = 0; o < NOUT; o++) op[o] = Lg[tid][o] - lse;
        }
    }
}

// ---------------------------------------------------------------------------
// Launch. Inputs (metadata order): hidden_states, pred_spans, token_num,
// span_available_indication_matrix, W1, b1, W2, b2. Output fp32 [16,3405,40].
// ---------------------------------------------------------------------------
extern "C" void kernel_launch(void* const* d_in, const int* in_sizes, int n_in,
                              void* d_out, int out_size) {
    const float* hidden = (const float*)d_in[0];
    const int*   spans  = (const int*)d_in[1];
    // d_in[2] token_num (==128) and d_in[3] span mask are implied by the
    // fixed band structure; pair table is rebuilt analytically each call.
    const float* W1 = (const float*)d_in[4];
    const float* b1 = (const float*)d_in[5];
    const float* W2 = (const float*)d_in[6];
    const float* b2 = (const float*)d_in[7];
    float* out = (float*)d_out;

    fill_pairs_kernel<<<1, 128>>>();
    gemm1_kernel<<<dim3((NH1 + BN - 1) / BN, (BATCH * SEQL) / BM, 2), 256>>>(hidden, W1);
    span_head_kernel<<<dim3((NPAIR + BP - 1) / BP, BATCH), 256>>>(W1, b1, W2, b2, spans, out);
}

// round 5
// speedup vs baseline: 1.3583x; 1.3580x over previous
#include <cuda_runtime.h>
#include <math.h>

// Shapes (fixed for this problem)
#define BATCH 16
#define SEQL  128
#define DIM   768
#define NH1   770
#define NOUT  40
#define NPAIR 3405
#define LP1   129     // L+1 rows per batch in hidden_states
#define PST   772     // padded row stride for P/Q (float4-aligned)

// Scratch: P = X @ W1i, Q = X @ W1j   (X = hidden[:,1:129,:] flattened, 2048 rows)
// Columns 770..771 of every row are explicitly zeroed by gemm1's last n-tile;
// span_head never reads past column 771, so no pad-region reads occur.
__device__ float g_P[(size_t)BATCH * SEQL * PST + 64];
__device__ float g_Q[(size_t)BATCH * SEQL * PST + 64];

// ---------------------------------------------------------------------------
// Kernel 1: 2048 x 768 x 770 fp32 GEMM. z=0 -> P (W1 rows 0..767),
//                                       z=1 -> Q (W1 rows 768..1535).
// 128x96 tile, 256 threads, 8x6 micro-tile, BK=16, single-sync double buffer.
// Grid = 9*16*2 = 288 blocks ~= 148 SMs * occ 2 -> one balanced wave.
// ---------------------------------------------------------------------------
#define BM 128
#define BN 96
#define BK 16
#define NKT (DIM / BK)   // 48

__global__ __launch_bounds__(256, 2)
void gemm1_kernel(const float* __restrict__ hidden, const float* __restrict__ W1) {
    const int n0 = blockIdx.x * BN;
    const int m0 = blockIdx.y * BM;
    const float* W = W1 + (size_t)blockIdx.z * DIM * NH1;
    float* Cout = (blockIdx.z == 0) ? g_P : g_Q;

    __shared__ float As[2][BK][BM];
    __shared__ float Bs[2][BK][BN];

    const int tid = threadIdx.x;
    const int tx  = tid & 15;   // 16 col groups x 6 cols
    const int ty  = tid >> 4;   // 16 row groups x 8 rows

    float acc[8][6];
    #pragma unroll
    for (int i = 0; i < 8; i++)
        #pragma unroll
        for (int j = 0; j < 6; j++) acc[i][j] = 0.f;

    // A-load mapping: 128 rows x 16 k = 2 float4 per thread
    const int a_k4 = tid & 3;    // float4 index within 16-wide k slab
    const int a_r  = tid >> 2;   // rows a_r, a_r + 64
    const float* aptr[2];
    #pragma unroll
    for (int rr = 0; rr < 2; rr++) {
        int m = m0 + a_r + rr * 64;
        int bb = m >> 7, t = m & 127;
        aptr[rr] = hidden + (size_t)(bb * LP1 + t + 1) * DIM + a_k4 * 4;
    }

    // B-load mapping: 16 k x 96 n = 6 scalars per thread (2 k-rows x 3 col-slots)
    const int lk   = tid >> 5;   // k rows lk, lk+8
    const int lcol = tid & 31;   // cols lcol, lcol+32, lcol+64
    bool bok[3];
    const float* bptr[3];
    #pragma unroll
    for (int c = 0; c < 3; c++) {
        int gc = n0 + lcol + 32 * c;
        bok[c]  = gc < NH1;
        bptr[c] = W + (bok[c] ? gc : 0);
    }

    float4 ra[2];
    float  rb[6];

    // prologue: load tile 0 straight into buffer 0
    #pragma unroll
    for (int rr = 0; rr < 2; rr++) ra[rr] = *(const float4*)(aptr[rr]);
    #pragma unroll
    for (int k2 = 0; k2 < 2; k2++)
        #pragma unroll
        for (int c = 0; c < 3; c++)
            rb[k2*3+c] = bok[c] ? bptr[c][(size_t)(lk + 8*k2) * NH1] : 0.f;

    #pragma unroll
    for (int rr = 0; rr < 2; rr++) {
        As[0][a_k4*4+0][a_r + rr*64] = ra[rr].x;
        As[0][a_k4*4+1][a_r + rr*64] = ra[rr].y;
        As[0][a_k4*4+2][a_r + rr*64] = ra[rr].z;
        As[0][a_k4*4+3][a_r + rr*64] = ra[rr].w;
    }
    #pragma unroll
    for (int k2 = 0; k2 < 2; k2++)
        #pragma unroll
        for (int c = 0; c < 3; c++)
            Bs[0][lk + 8*k2][lcol + 32*c] = rb[k2*3+c];
    __syncthreads();

    int cur = 0;
    for (int kt = 0; kt < NKT; kt++) {
        const int k0n = (kt + 1) * BK;
        if (kt + 1 < NKT) {
            #pragma unroll
            for (int rr = 0; rr < 2; rr++) ra[rr] = *(const float4*)(aptr[rr] + k0n);
            #pragma unroll
            for (int k2 = 0; k2 < 2; k2++)
                #pragma unroll
                for (int c = 0; c < 3; c++)
                    rb[k2*3+c] = bok[c] ? bptr[c][(size_t)(k0n + lk + 8*k2) * NH1] : 0.f;
        }

        #pragma unroll
        for (int kk = 0; kk < BK; kk++) {
            float4 a0 = *(const float4*)&As[cur][kk][ty*8];
            float4 a1 = *(const float4*)&As[cur][kk][ty*8 + 4];
            float2 b0 = *(const float2*)&Bs[cur][kk][tx*6];
            float2 b1 = *(const float2*)&Bs[cur][kk][tx*6 + 2];
            float2 b2 = *(const float2*)&Bs[cur][kk][tx*6 + 4];
            float av[8] = {a0.x,a0.y,a0.z,a0.w,a1.x,a1.y,a1.z,a1.w};
            float bv[6] = {b0.x,b0.y,b1.x,b1.y,b2.x,b2.y};
            #pragma unroll
            for (int i = 0; i < 8; i++)
                #pragma unroll
                for (int j = 0; j < 6; j++)
                    acc[i][j] = fmaf(av[i], bv[j], acc[i][j]);
        }

        if (kt + 1 < NKT) {
            int nxt = cur ^ 1;
            #pragma unroll
            for (int rr = 0; rr < 2; rr++) {
                As[nxt][a_k4*4+0][a_r + rr*64] = ra[rr].x;
                As[nxt][a_k4*4+1][a_r + rr*64] = ra[rr].y;
                As[nxt][a_k4*4+2][a_r + rr*64] = ra[rr].z;
                As[nxt][a_k4*4+3][a_r + rr*64] = ra[rr].w;
            }
            #pragma unroll
            for (int k2 = 0; k2 < 2; k2++)
                #pragma unroll
                for (int c = 0; c < 3; c++)
                    Bs[nxt][lk + 8*k2][lcol + 32*c] = rb[k2*3+c];
        }
        __syncthreads();
        cur ^= 1;
    }

    #pragma unroll
    for (int i = 0; i < 8; i++) {
        size_t mrow = (size_t)(m0 + ty*8 + i) * PST;
        #pragma unroll
        for (int j = 0; j < 6; j++) {
            int nn = n0 + tx*6 + j;
            if (nn < NH1)      Cout[mrow + nn] = acc[i][j];
            else if (nn < PST) Cout[mrow + nn] = 0.f;  // zero cols 770..771
        }
    }
}

// ---------------------------------------------------------------------------
// Kernel 2: per (batch, 128-pair chunk):
//   Ht[k][r] = relu(P[vi_r][k] + Q[vj_r][k] + ind_r*w1c[k] + b1[k])
//   logits   = Ht^T @ W2 + b2, log_softmax fused via 8-lane shuffles.
// 128 threads, 8x5 register micro-tile, K tiles of 32.
// ---------------------------------------------------------------------------
#define BP  128
#define BK2 32
#define HTS (BP + 4)   // 132, float4-aligned rows

__global__ __launch_bounds__(128, 4)
void span_head_kernel(const float* __restrict__ W1, const float* __restrict__ bias1,
                      const float* __restrict__ W2, const float* __restrict__ bias2,
                      const int* __restrict__ spans, float* __restrict__ out) {
    const int b   = blockIdx.y;
    const int p0  = blockIdx.x * BP;
    const int tid = threadIdx.x;

    __shared__ float Ht[BK2][HTS];
    __shared__ float W2s[BK2 * NOUT];
    __shared__ int   s_ri[BP];
    __shared__ int   s_rj[BP];
    __shared__ float s_ind[BP];

    const float* w1c = W1 + (size_t)2 * DIM * NH1;  // row 1536 of W1

    // Analytic pair decode: nonzero order of the (j>=i, j-i<30) band, L=128.
    {
        int p  = p0 + tid;
        int pc = (p < NPAIR) ? p : (NPAIR - 1);
        int i, j;
        if (pc < 2970) {
            i = pc / 30;
            j = i + (pc - 30 * i);
        } else {
            int q = pc - 2970;                        // 0..434, tail rows 99..127
            int d = (int)(29.5f - sqrtf(870.25f - 2.0f * (float)q));
            while ((d + 1) * (58 - d) / 2 <= q) d++;  // S(d+1) = (d+1)(59-(d+1))/2
            while (d * (59 - d) / 2 > q) d--;
            i = 99 + d;
            j = i + (q - d * (59 - d) / 2);
        }
        float ind = 0.f;
        if (p < NPAIR) {
            int s = spans[b*2 + 0];
            int e = spans[b*2 + 1];
            if (i == s && j == e)      ind = 2.f;
            else if (i >= s && j <= e) ind = 1.f;
        }
        s_ri[tid]  = (b * SEQL + i) * PST;
        s_rj[tid]  = (b * SEQL + j) * PST;
        s_ind[tid] = ind;
    }
    __syncthreads();

    const int tx   = tid & 7;    // 8 col groups x 5 outputs
    const int ty   = tid >> 3;   // 16 row groups x 8 rows
    const int g_kq = tid & 7;    // float4 index within 32-wide k slab
    const int g_r0 = tid >> 3;   // gather rows g_r0 + 16w

    float acc[8][5];
    #pragma unroll
    for (int i = 0; i < 8; i++)
        #pragma unroll
        for (int j = 0; j < 5; j++) acc[i][j] = 0.f;

    for (int k0 = 0; k0 < NH1; k0 += BK2) {
        // W2 tile: 32x40 = 1280 floats, coalesced (zeros past 770 kill garbage k)
        #pragma unroll
        for (int u = 0; u < 10; u++) {
            int idx = u * 128 + tid;
            int g   = k0 * NOUT + idx;
            W2s[idx] = (g < NH1 * NOUT) ? W2[g] : 0.f;
        }

        const int kb = k0 + g_kq * 4;
        const int kl = g_kq * 4;
        if (kb < PST) {   // kb <= 768: P/Q cols valid (770/771 are zeroed)
            float4 c1, c2;
            if (kb + 3 < NH1) {
                c1 = *(const float4*)(w1c + kb);
                c2 = *(const float4*)(bias1 + kb);
            } else {
                c1.x = (kb+0 < NH1) ? w1c[kb+0] : 0.f;
                c1.y = (kb+1 < NH1) ? w1c[kb+1] : 0.f;
                c1.z = (kb+2 < NH1) ? w1c[kb+2] : 0.f;
                c1.w = (kb+3 < NH1) ? w1c[kb+3] : 0.f;
                c2.x = (kb+0 < NH1) ? bias1[kb+0] : 0.f;
                c2.y = (kb+1 < NH1) ? bias1[kb+1] : 0.f;
                c2.z = (kb+2 < NH1) ? bias1[kb+2] : 0.f;
                c2.w = (kb+3 < NH1) ? bias1[kb+3] : 0.f;
            }
            #pragma unroll
            for (int w = 0; w < 8; w++) {
                int r = g_r0 + w * 16;
                float4 p4 = *(const float4*)(g_P + s_ri[r] + kb);
                float4 q4 = *(const float4*)(g_Q + s_rj[r] + kb);
                float ind = s_ind[r];
                Ht[kl+0][r] = fmaxf(fmaf(ind, c1.x, p4.x + q4.x + c2.x), 0.f);
                Ht[kl+1][r] = fmaxf(fmaf(ind, c1.y, p4.y + q4.y + c2.y), 0.f);
                Ht[kl+2][r] = fmaxf(fmaf(ind, c1.z, p4.z + q4.z + c2.z), 0.f);
                Ht[kl+3][r] = fmaxf(fmaf(ind, c1.w, p4.w + q4.w + c2.w), 0.f);
            }
        } else {          // k >= 772: never load (pad is uninitialized) — zero it
            #pragma unroll
            for (int w = 0; w < 8; w++) {
                int r = g_r0 + w * 16;
                Ht[kl+0][r] = 0.f; Ht[kl+1][r] = 0.f;
                Ht[kl+2][r] = 0.f; Ht[kl+3][r] = 0.f;
            }
        }
        __syncthreads();

        #pragma unroll
        for (int kk = 0; kk < BK2; kk++) {
            float4 a0 = *(const float4*)&Ht[kk][ty*8];
            float4 a1 = *(const float4*)&Ht[kk][ty*8 + 4];
            const float* wrow = &W2s[kk * NOUT + tx * 5];
            float b0 = wrow[0], b1v = wrow[1], b2v = wrow[2], b3v = wrow[3], b4v = wrow[4];
            float av[8] = {a0.x,a0.y,a0.z,a0.w,a1.x,a1.y,a1.z,a1.w};
            #pragma unroll
            for (int i = 0; i < 8; i++) {
                acc[i][0] = fmaf(av[i], b0,  acc[i][0]);
                acc[i][1] = fmaf(av[i], b1v, acc[i][1]);
                acc[i][2] = fmaf(av[i], b2v, acc[i][2]);
                acc[i][3] = fmaf(av[i], b3v, acc[i][3]);
                acc[i][4] = fmaf(av[i], b4v, acc[i][4]);
            }
        }
        __syncthreads();
    }

    // bias + log_softmax per row via 8-lane butterfly (lanes tx=0..7 of same ty),
    // store straight from registers (no Lg smem, no extra barrier).
    float bb[5];
    #pragma unroll
    for (int j = 0; j < 5; j++) bb[j] = bias2[tx*5 + j];

    #pragma unroll
    for (int i = 0; i < 8; i++) {
        float l[5];
        #pragma unroll
        for (int j = 0; j < 5; j++) l[j] = acc[i][j] + bb[j];
        float mx = l[0];
        #pragma unroll
        for (int j = 1; j < 5; j++) mx = fmaxf(mx, l[j]);
        mx = fmaxf(mx, __shfl_xor_sync(0xffffffffu, mx, 1));
        mx = fmaxf(mx, __shfl_xor_sync(0xffffffffu, mx, 2));
        mx = fmaxf(mx, __shfl_xor_sync(0xffffffffu, mx, 4));
        float sm = 0.f;
        #pragma unroll
        for (int j = 0; j < 5; j++) sm += expf(l[j] - mx);
        sm += __shfl_xor_sync(0xffffffffu, sm, 1);
        sm += __shfl_xor_sync(0xffffffffu, sm, 2);
        sm += __shfl_xor_sync(0xffffffffu, sm, 4);
        float lse = mx + logf(sm);

        int p_row = p0 + ty*8 + i;
        if (p_row < NPAIR) {
            float* op = out + ((size_t)b * NPAIR + p_row) * NOUT + tx * 5;
            #pragma unroll
            for (int j = 0; j < 5; j++) op[j] = l[j] - lse;
        }
    }
}

// ---------------------------------------------------------------------------
// Launch. Inputs (metadata order): hidden_states, pred_spans, token_num,
// span_available_indication_matrix, W1, b1, W2, b2. Output fp32 [16,3405,40].
// ---------------------------------------------------------------------------
extern "C" void kernel_launch(void* const* d_in, const int* in_sizes, int n_in,
                              void* d_out, int out_size) {
    const float* hidden = (const float*)d_in[0];
    const int*   spans  = (const int*)d_in[1];
    const float* W1 = (const float*)d_in[4];
    const float* b1 = (const float*)d_in[5];
    const float* W2 = (const float*)d_in[6];
    const float* b2 = (const float*)d_in[7];
    float* out = (float*)d_out;

    gemm1_kernel<<<dim3((NH1 + BN - 1) / BN, (BATCH * SEQL) / BM, 2), 256>>>(hidden, W1);
    span_head_kernel<<<dim3((NPAIR + BP - 1) / BP, BATCH), 128>>>(W1, b1, W2, b2, spans, out);
}